// round 5
// baseline (speedup 1.0000x reference)
#include <cuda_runtime.h>
#include <cuda_fp16.h>
#include <mma.h>
#include <math.h>

using namespace nvcuda;

#define N_NODES  50000
#define N_EDGES  600000
#define N_GRAPHS 64
#define IN_C  128
#define HID_C 128
#define OUT_C 64
#define NBLK  196            // ceil(50000/256)

// ---------------- scratch (device globals; zero-initialized, no allocation) -----
__device__ int    d_cnt[N_NODES];        // zeroed at end of each run by k_scanC
__device__ int    d_rowptr[N_NODES + 1];
__device__ int    d_cursor[N_NODES];
__device__ int    d_part[NBLK];
__device__ int    d_col[N_EDGES];
__device__ float  d_dinv[N_NODES];
__device__ __half d_gh [N_NODES * HID_C];   // x @ W1 (UNscaled), fp16
__device__ __half d_g2h[N_NODES * HID_C];   // dinv * relu(...), fp16 (pre-scaled)
__device__ float  d_pool[N_GRAPHS * HID_C];
__device__ int    d_start[N_GRAPHS + 1];
__device__ unsigned d_done;              // last-block counter (self-resetting)

// ---------------- helpers ----------------
__device__ __forceinline__ float4 h4_to_f4(uint2 u) {
    __half2 a = *(__half2*)&u.x, b = *(__half2*)&u.y;
    float2 fa = __half22float2(a), fb = __half22float2(b);
    return make_float4(fa.x, fa.y, fb.x, fb.y);
}
__device__ __forceinline__ uint2 f4_to_h4(float4 v) {
    __half2 a = __floats2half2_rn(v.x, v.y), b = __floats2half2_rn(v.z, v.w);
    uint2 u; u.x = *(unsigned*)&a; u.y = *(unsigned*)&b; return u;
}

// ---------------- histogram over dst (int4-vectorized) ----------------
__global__ void k_hist(const int* __restrict__ edge) {
    int t = blockIdx.x * blockDim.x + threadIdx.x;
    if (t >= N_EDGES / 4) return;
    int4 d = ((const int4*)(edge + N_EDGES))[t];
    if ((unsigned)d.x < N_NODES) atomicAdd(&d_cnt[d.x], 1);
    if ((unsigned)d.y < N_NODES) atomicAdd(&d_cnt[d.y], 1);
    if ((unsigned)d.z < N_NODES) atomicAdd(&d_cnt[d.z], 1);
    if ((unsigned)d.w < N_NODES) atomicAdd(&d_cnt[d.w], 1);
}

// ---------------- scan A: per-block excl scan + block totals ----------------
__global__ __launch_bounds__(256) void k_scanA() {
    __shared__ int wsum[8];
    int tid = threadIdx.x, lane = tid & 31, wid = tid >> 5;
    int i = blockIdx.x * 256 + tid;
    int v = (i < N_NODES) ? d_cnt[i] : 0;
    int x = v;
    #pragma unroll
    for (int d = 1; d < 32; d <<= 1) {
        int t = __shfl_up_sync(0xffffffffu, x, d);
        if (lane >= d) x += t;
    }
    if (lane == 31) wsum[wid] = x;
    __syncthreads();
    if (wid == 0 && lane < 8) {
        int y = wsum[lane];
        #pragma unroll
        for (int d = 1; d < 8; d <<= 1) {
            int t = __shfl_up_sync(0x000000ffu, y, d);
            if (lane >= d) y += t;
        }
        wsum[lane] = y;
    }
    __syncthreads();
    int excl = (x - v) + (wid > 0 ? wsum[wid - 1] : 0);
    if (i < N_NODES) d_cursor[i] = excl;
    if (tid == 0) d_part[blockIdx.x] = wsum[7];
}

// ---------------- scan C: per-block prefix of partials + fixup + dinv + bounds --
__global__ __launch_bounds__(256) void k_scanC(const int* __restrict__ batch) {
    __shared__ int red[256];
    __shared__ int s_prefix, s_total;
    int tid = threadIdx.x, blk = blockIdx.x;
    int p = (tid < NBLK) ? d_part[tid] : 0;
    red[tid] = (tid < blk) ? p : 0;
    __syncthreads();
    for (int off = 128; off > 0; off >>= 1) {
        if (tid < off) red[tid] += red[tid + off];
        __syncthreads();
    }
    if (tid == 0) s_prefix = red[0];
    __syncthreads();
    red[tid] = p;
    __syncthreads();
    for (int off = 128; off > 0; off >>= 1) {
        if (tid < off) red[tid] += red[tid + off];
        __syncthreads();
    }
    if (tid == 0) s_total = red[0];
    __syncthreads();
    if (blk == 0 && tid == 0) d_rowptr[N_NODES] = s_total;
    int i = blk * 256 + tid;
    if (i >= N_NODES) return;
    int v = d_cnt[i];
    d_cnt[i] = 0;                       // reset for next replay
    int excl = d_cursor[i] + s_prefix;
    d_rowptr[i] = excl;
    d_cursor[i] = excl;
    d_dinv[i] = rsqrtf((float)(v + 1));
    int b  = min(max(batch[i], 0), N_GRAPHS - 1);
    int bp = (i == 0) ? -1 : min(max(batch[i - 1], 0), N_GRAPHS - 1);
    for (int gg = bp + 1; gg <= b; gg++) d_start[gg] = i;
    if (i == N_NODES - 1)
        for (int gg = b + 1; gg <= N_GRAPHS; gg++) d_start[gg] = N_NODES;
}

// ---------------- CSR scatter (int4-vectorized) ----------------
__global__ void k_scatter(const int* __restrict__ edge) {
    int t = blockIdx.x * blockDim.x + threadIdx.x;
    if (t >= N_EDGES / 4) return;
    int4 s4 = ((const int4*)edge)[t];
    int4 d4 = ((const int4*)(edge + N_EDGES))[t];
    #pragma unroll
    for (int k = 0; k < 4; k++) {
        int src = (&s4.x)[k], dst = (&d4.x)[k];
        if ((unsigned)src < N_NODES && (unsigned)dst < N_NODES) {
            int p = atomicAdd(&d_cursor[dst], 1);
            d_col[p] = src;
        }
    }
}

// ---------------- GEMM1 (tensor cores): d_gh = fp16( x @ W1 ) -------------------
// No dependency on the CSR chain -> runs on a forked stream. Block 0 zeros pool.
#define ASTR 136
#define GEMM_SMEM_BYTES (2 * 128 * ASTR * 2)
__global__ __launch_bounds__(256) void k_gemm1(const float* __restrict__ x,
                                               const float* __restrict__ W1) {
    extern __shared__ char smraw[];
    __half* As = (__half*)smraw;
    __half* Bs = As + 128 * ASTR;
    float*  Cs = (float*)smraw;
    int row0 = blockIdx.x * 128;
    int tid = threadIdx.x, wid = tid >> 5;

    if (blockIdx.x == 0)
        for (int i = tid; i < N_GRAPHS * HID_C; i += 256) d_pool[i] = 0.0f;

    for (int i = tid; i < 4096; i += 256) {
        int r = i >> 5, c4 = i & 31;
        int gr = row0 + r;
        float4 v = make_float4(0.f, 0.f, 0.f, 0.f);
        if (gr < N_NODES) v = ((const float4*)(x + (size_t)gr * IN_C))[c4];
        *(uint2*)&As[r * ASTR + c4 * 4] = f4_to_h4(v);
    }
    for (int i = tid; i < 4096; i += 256) {
        float4 v = ((const float4*)W1)[i];
        int r = i >> 5, c4 = i & 31;
        *(uint2*)&Bs[r * ASTR + c4 * 4] = f4_to_h4(v);
    }
    __syncthreads();

    wmma::fragment<wmma::accumulator, 16, 16, 16, float> acc[8];
    #pragma unroll
    for (int n = 0; n < 8; n++) wmma::fill_fragment(acc[n], 0.0f);

    #pragma unroll
    for (int kk = 0; kk < 8; kk++) {
        wmma::fragment<wmma::matrix_a, 16, 16, 16, __half, wmma::row_major> af;
        wmma::load_matrix_sync(af, &As[(wid * 16) * ASTR + kk * 16], ASTR);
        #pragma unroll
        for (int n = 0; n < 8; n++) {
            wmma::fragment<wmma::matrix_b, 16, 16, 16, __half, wmma::row_major> bf;
            wmma::load_matrix_sync(bf, &Bs[(kk * 16) * ASTR + n * 16], ASTR);
            wmma::mma_sync(acc[n], af, bf, acc[n]);
        }
    }
    __syncthreads();

    #pragma unroll
    for (int n = 0; n < 8; n++)
        wmma::store_matrix_sync(&Cs[(wid * 16) * 128 + n * 16], acc[n], 128,
                                wmma::mem_row_major);
    __syncthreads();

    for (int i = tid; i < 4096; i += 256) {
        int r = i >> 5, c4 = i & 31;
        int gr = row0 + r;
        if (gr < N_NODES) {
            float4 v = *(float4*)&Cs[r * 128 + c4 * 4];
            *(uint2*)&d_gh[(size_t)gr * HID_C + c4 * 4] = f4_to_h4(v);
        }
    }
}

// ---------------- layer-1 aggregate: warp/node, dinv-at-gather, unroll 8 --------
__global__ __launch_bounds__(256) void k_agg1(const float* __restrict__ b1) {
    int gw   = blockIdx.x * 8 + (threadIdx.x >> 5);
    int lane = threadIdx.x & 31;
    if (gw >= N_NODES) return;
    const uint2* g2 = (const uint2*)d_gh;
    float dj = __ldg(&d_dinv[gw]);
    float4 h0 = h4_to_f4(g2[(size_t)gw * 32 + lane]);
    float4 s = make_float4(h0.x * dj, h0.y * dj, h0.z * dj, h0.w * dj);
    int e0 = __ldg(&d_rowptr[gw]), e1 = __ldg(&d_rowptr[gw + 1]);
    for (int e = e0; e < e1; e += 8) {
        int sn[8]; float dv[8]; uint2 vv[8];
        #pragma unroll
        for (int k = 0; k < 8; k++) {
            int idx = e + k;
            sn[k] = __ldg(&d_col[idx < e1 ? idx : e1 - 1]);
        }
        #pragma unroll
        for (int k = 0; k < 8; k++)
            dv[k] = (e + k < e1) ? __ldg(&d_dinv[sn[k]]) : 0.0f;
        #pragma unroll
        for (int k = 0; k < 8; k++)
            vv[k] = __ldg(&g2[(size_t)sn[k] * 32 + lane]);
        #pragma unroll
        for (int k = 0; k < 8; k++) {
            float4 f = h4_to_f4(vv[k]);
            s.x = fmaf(f.x, dv[k], s.x);
            s.y = fmaf(f.y, dv[k], s.y);
            s.z = fmaf(f.z, dv[k], s.z);
            s.w = fmaf(f.w, dv[k], s.w);
        }
    }
    float4 bb = __ldg(&((const float4*)b1)[lane]);
    float4 o;
    o.x = fmaxf(fmaf(s.x, dj, bb.x), 0.f) * dj;
    o.y = fmaxf(fmaf(s.y, dj, bb.y), 0.f) * dj;
    o.z = fmaxf(fmaf(s.z, dj, bb.z), 0.f) * dj;
    o.w = fmaxf(fmaf(s.w, dj, bb.w), 0.f) * dj;
    ((uint2*)d_g2h)[(size_t)gw * 32 + lane] = f4_to_h4(o);
}

// ---------------- layer-2 aggregate + pool atomics + fused final GEMM -----------
__global__ __launch_bounds__(256) void k_agg2f(const int* __restrict__ batch,
                                               const float* __restrict__ W2,
                                               const float* __restrict__ b2,
                                               float* __restrict__ out) {
    int tid  = threadIdx.x;
    int gw   = blockIdx.x * 8 + (tid >> 5);
    int lane = tid & 31;
    if (gw < N_NODES) {
        const uint2* g2 = (const uint2*)d_g2h;
        float4 s = h4_to_f4(g2[(size_t)gw * 32 + lane]);   // self (pre-scaled)
        int e0 = __ldg(&d_rowptr[gw]), e1 = __ldg(&d_rowptr[gw + 1]);
        for (int e = e0; e < e1; e += 8) {
            int sn[8]; float w[8]; uint2 vv[8];
            #pragma unroll
            for (int k = 0; k < 8; k++) {
                int idx = e + k;
                sn[k] = __ldg(&d_col[idx < e1 ? idx : e1 - 1]);
                w[k] = (idx < e1) ? 1.0f : 0.0f;
            }
            #pragma unroll
            for (int k = 0; k < 8; k++)
                vv[k] = __ldg(&g2[(size_t)sn[k] * 32 + lane]);
            #pragma unroll
            for (int k = 0; k < 8; k++) {
                float4 f = h4_to_f4(vv[k]);
                s.x = fmaf(f.x, w[k], s.x);
                s.y = fmaf(f.y, w[k], s.y);
                s.z = fmaf(f.z, w[k], s.z);
                s.w = fmaf(f.w, w[k], s.w);
            }
        }
        float dj = __ldg(&d_dinv[gw]);
        int bg = min(max(batch[gw], 0), N_GRAPHS - 1);
        float* p = &d_pool[bg * HID_C + lane * 4];
        atomicAdd(p + 0, s.x * dj);
        atomicAdd(p + 1, s.y * dj);
        atomicAdd(p + 2, s.z * dj);
        atomicAdd(p + 3, s.w * dj);
    }
    // ---- last-block fused final ----
    __threadfence();
    __shared__ bool isLast;
    if (tid == 0) {
        unsigned t = atomicAdd(&d_done, 1u);
        isLast = (t == gridDim.x - 1);
        if (isLast) d_done = 0;            // reset for next replay
    }
    __syncthreads();
    if (!isLast) return;
    __threadfence();
    int g = tid >> 2;                      // 64 graphs
    int c0 = (tid & 3) * 16;               // 16 output cols per thread
    int cnt = d_start[g + 1] - d_start[g];
    float inv = 1.0f / (float)max(cnt, 1);
    float acc[16];
    #pragma unroll
    for (int j = 0; j < 16; j++) acc[j] = 0.f;
    for (int k = 0; k < HID_C; k++) {
        float pv = d_pool[g * HID_C + k];
        #pragma unroll
        for (int j = 0; j < 16; j++)
            acc[j] = fmaf(pv, __ldg(&W2[k * OUT_C + c0 + j]), acc[j]);
    }
    #pragma unroll
    for (int j = 0; j < 16; j++)
        out[g * OUT_C + c0 + j] = acc[j] * inv + (cnt > 0 ? __ldg(&b2[c0 + j]) : 0.f);
}

// ---------------- launch ----------------
extern "C" void kernel_launch(void* const* d_in, const int* in_sizes, int n_in,
                              void* d_out, int out_size) {
    const float *x = nullptr, *W1 = nullptr, *b1 = nullptr, *W2 = nullptr, *b2 = nullptr;
    const int *edge = nullptr, *batch = nullptr;
    for (int i = 0; i < n_in; i++) {
        switch (in_sizes[i]) {
            case N_NODES * IN_C:  x     = (const float*)d_in[i]; break;
            case IN_C * HID_C:    W1    = (const float*)d_in[i]; break;
            case HID_C:           b1    = (const float*)d_in[i]; break;
            case HID_C * OUT_C:   W2    = (const float*)d_in[i]; break;
            case OUT_C:           b2    = (const float*)d_in[i]; break;
            case 2 * N_EDGES:     edge  = (const int*)d_in[i];   break;
            case N_NODES:         batch = (const int*)d_in[i];   break;
            default: break;
        }
    }

    static cudaStream_t s2 = nullptr;
    static cudaEvent_t evF = nullptr, evJ = nullptr;
    if (!s2) {
        cudaStreamCreateWithFlags(&s2, cudaStreamNonBlocking);
        cudaEventCreateWithFlags(&evF, cudaEventDisableTiming);
        cudaEventCreateWithFlags(&evJ, cudaEventDisableTiming);
    }

    cudaFuncSetAttribute(k_gemm1, cudaFuncAttributeMaxDynamicSharedMemorySize,
                         GEMM_SMEM_BYTES);

    // fork: gemm1 is independent of the CSR build
    cudaEventRecord(evF, 0);
    cudaStreamWaitEvent(s2, evF, 0);

    k_hist<<<(N_EDGES / 4 + 255) / 256, 256>>>(edge);
    k_scanA<<<NBLK, 256>>>();
    k_scanC<<<NBLK, 256>>>(batch);
    k_gemm1<<<(N_NODES + 127) / 128, 256, GEMM_SMEM_BYTES, s2>>>(x, W1);
    k_scatter<<<(N_EDGES / 4 + 255) / 256, 256>>>(edge);

    // join
    cudaEventRecord(evJ, s2);
    cudaStreamWaitEvent(0, evJ, 0);

    k_agg1<<<(N_NODES + 7) / 8, 256>>>(b1);
    k_agg2f<<<(N_NODES + 7) / 8, 256>>>(batch, W2, b2, (float*)d_out);
}

// round 6
// speedup vs baseline: 1.0431x; 1.0431x over previous
#include <cuda_runtime.h>
#include <cuda_fp16.h>
#include <mma.h>
#include <math.h>

using namespace nvcuda;

#define N_NODES  50000
#define N_EDGES  600000
#define N_GRAPHS 64
#define IN_C  128
#define HID_C 128
#define OUT_C 64
#define NBLK  196            // ceil(50000/256)

// ---------------- scratch (device globals; zero-initialized, no allocation) -----
__device__ int    d_cnt[N_NODES];        // self-resetting (zeroed by k_scanC)
__device__ int    d_rowptr[N_NODES + 1];
__device__ int    d_cursor[N_NODES];
__device__ int    d_part[NBLK];
__device__ int    d_col[N_EDGES];
__device__ float  d_dinv[N_NODES];
__device__ __half d_gh [N_NODES * HID_C];   // dinv * (x @ W1), fp16 (pre-scaled)
__device__ __half d_g2h[N_NODES * HID_C];   // dinv * relu(...), fp16 (pre-scaled)
__device__ float  d_pool[N_GRAPHS * HID_C];
__device__ int    d_start[N_GRAPHS + 1];
__device__ unsigned d_done;              // last-block counter (self-resetting)

// ---------------- helpers ----------------
__device__ __forceinline__ float4 h4_to_f4(uint2 u) {
    __half2 a = *(__half2*)&u.x, b = *(__half2*)&u.y;
    float2 fa = __half22float2(a), fb = __half22float2(b);
    return make_float4(fa.x, fa.y, fb.x, fb.y);
}
__device__ __forceinline__ uint2 f4_to_h4(float4 v) {
    __half2 a = __floats2half2_rn(v.x, v.y), b = __floats2half2_rn(v.z, v.w);
    uint2 u; u.x = *(unsigned*)&a; u.y = *(unsigned*)&b; return u;
}

// ---------------- 1. histogram over dst (int4-vectorized) ----------------
__global__ void k_hist(const int* __restrict__ edge) {
    int t = blockIdx.x * blockDim.x + threadIdx.x;
    if (t >= N_EDGES / 4) return;
    int4 d = ((const int4*)(edge + N_EDGES))[t];
    if ((unsigned)d.x < N_NODES) atomicAdd(&d_cnt[d.x], 1);
    if ((unsigned)d.y < N_NODES) atomicAdd(&d_cnt[d.y], 1);
    if ((unsigned)d.z < N_NODES) atomicAdd(&d_cnt[d.z], 1);
    if ((unsigned)d.w < N_NODES) atomicAdd(&d_cnt[d.w], 1);
}

// ---------------- 2. scan A: per-block excl scan + block totals ----------------
__global__ __launch_bounds__(256) void k_scanA() {
    __shared__ int wsum[8];
    int tid = threadIdx.x, lane = tid & 31, wid = tid >> 5;
    int i = blockIdx.x * 256 + tid;
    int v = (i < N_NODES) ? d_cnt[i] : 0;
    int x = v;
    #pragma unroll
    for (int d = 1; d < 32; d <<= 1) {
        int t = __shfl_up_sync(0xffffffffu, x, d);
        if (lane >= d) x += t;
    }
    if (lane == 31) wsum[wid] = x;
    __syncthreads();
    if (wid == 0 && lane < 8) {
        int y = wsum[lane];
        #pragma unroll
        for (int d = 1; d < 8; d <<= 1) {
            int t = __shfl_up_sync(0x000000ffu, y, d);
            if (lane >= d) y += t;
        }
        wsum[lane] = y;
    }
    __syncthreads();
    int excl = (x - v) + (wid > 0 ? wsum[wid - 1] : 0);
    if (i < N_NODES) d_cursor[i] = excl;
    if (tid == 0) d_part[blockIdx.x] = wsum[7];
}

// ---------------- 3. scan C: block prefix of partials + fixup + dinv + bounds ---
__global__ __launch_bounds__(256) void k_scanC(const int* __restrict__ batch) {
    __shared__ int red[256];
    __shared__ int s_prefix, s_total;
    int tid = threadIdx.x, blk = blockIdx.x;
    int p = (tid < NBLK) ? d_part[tid] : 0;
    red[tid] = (tid < blk) ? p : 0;
    __syncthreads();
    for (int off = 128; off > 0; off >>= 1) {
        if (tid < off) red[tid] += red[tid + off];
        __syncthreads();
    }
    if (tid == 0) s_prefix = red[0];
    __syncthreads();
    red[tid] = p;
    __syncthreads();
    for (int off = 128; off > 0; off >>= 1) {
        if (tid < off) red[tid] += red[tid + off];
        __syncthreads();
    }
    if (tid == 0) s_total = red[0];
    __syncthreads();
    if (blk == 0 && tid == 0) d_rowptr[N_NODES] = s_total;
    int i = blk * 256 + tid;
    if (i >= N_NODES) return;
    int v = d_cnt[i];
    d_cnt[i] = 0;                       // reset for next replay
    int excl = d_cursor[i] + s_prefix;
    d_rowptr[i] = excl;
    d_cursor[i] = excl;
    d_dinv[i] = rsqrtf((float)(v + 1));
    int b  = min(max(batch[i], 0), N_GRAPHS - 1);
    int bp = (i == 0) ? -1 : min(max(batch[i - 1], 0), N_GRAPHS - 1);
    for (int gg = bp + 1; gg <= b; gg++) d_start[gg] = i;
    if (i == N_NODES - 1)
        for (int gg = b + 1; gg <= N_GRAPHS; gg++) d_start[gg] = N_NODES;
}

// ---------------- 4. CSR scatter (int4-vectorized) ----------------
__global__ void k_scatter(const int* __restrict__ edge) {
    int t = blockIdx.x * blockDim.x + threadIdx.x;
    if (t >= N_EDGES / 4) return;
    int4 s4 = ((const int4*)edge)[t];
    int4 d4 = ((const int4*)(edge + N_EDGES))[t];
    #pragma unroll
    for (int k = 0; k < 4; k++) {
        int src = (&s4.x)[k], dst = (&d4.x)[k];
        if ((unsigned)src < N_NODES && (unsigned)dst < N_NODES) {
            int p = atomicAdd(&d_cursor[dst], 1);
            d_col[p] = src;
        }
    }
}

// ---------------- 5. GEMM1 (tensor cores): d_gh = fp16( dinv * (x @ W1) ) ------
#define ASTR 136
#define GEMM_SMEM_BYTES (2 * 128 * ASTR * 2)
__global__ __launch_bounds__(256) void k_gemm1(const float* __restrict__ x,
                                               const float* __restrict__ W1) {
    extern __shared__ char smraw[];
    __half* As = (__half*)smraw;
    __half* Bs = As + 128 * ASTR;
    float*  Cs = (float*)smraw;
    int row0 = blockIdx.x * 128;
    int tid = threadIdx.x, wid = tid >> 5;

    if (blockIdx.x == 0)
        for (int i = tid; i < N_GRAPHS * HID_C; i += 256) d_pool[i] = 0.0f;

    for (int i = tid; i < 4096; i += 256) {
        int r = i >> 5, c4 = i & 31;
        int gr = row0 + r;
        float4 v = make_float4(0.f, 0.f, 0.f, 0.f);
        if (gr < N_NODES) v = ((const float4*)(x + (size_t)gr * IN_C))[c4];
        *(uint2*)&As[r * ASTR + c4 * 4] = f4_to_h4(v);
    }
    for (int i = tid; i < 4096; i += 256) {
        float4 v = ((const float4*)W1)[i];
        int r = i >> 5, c4 = i & 31;
        *(uint2*)&Bs[r * ASTR + c4 * 4] = f4_to_h4(v);
    }
    __syncthreads();

    wmma::fragment<wmma::accumulator, 16, 16, 16, float> acc[8];
    #pragma unroll
    for (int n = 0; n < 8; n++) wmma::fill_fragment(acc[n], 0.0f);

    #pragma unroll
    for (int kk = 0; kk < 8; kk++) {
        wmma::fragment<wmma::matrix_a, 16, 16, 16, __half, wmma::row_major> af;
        wmma::load_matrix_sync(af, &As[(wid * 16) * ASTR + kk * 16], ASTR);
        #pragma unroll
        for (int n = 0; n < 8; n++) {
            wmma::fragment<wmma::matrix_b, 16, 16, 16, __half, wmma::row_major> bf;
            wmma::load_matrix_sync(bf, &Bs[(kk * 16) * ASTR + n * 16], ASTR);
            wmma::mma_sync(acc[n], af, bf, acc[n]);
        }
    }
    __syncthreads();

    #pragma unroll
    for (int n = 0; n < 8; n++)
        wmma::store_matrix_sync(&Cs[(wid * 16) * 128 + n * 16], acc[n], 128,
                                wmma::mem_row_major);
    __syncthreads();

    for (int i = tid; i < 4096; i += 256) {
        int r = i >> 5, c4 = i & 31;
        int gr = row0 + r;
        if (gr < N_NODES) {
            float dv = __ldg(&d_dinv[gr]);
            float4 v = *(float4*)&Cs[r * 128 + c4 * 4];
            v.x *= dv; v.y *= dv; v.z *= dv; v.w *= dv;
            *(uint2*)&d_gh[(size_t)gr * HID_C + c4 * 4] = f4_to_h4(v);
        }
    }
}

// ---------------- 6. layer-1 aggregate: warp per node (round-4 form) ------------
__global__ __launch_bounds__(256) void k_agg1(const float* __restrict__ b1) {
    int gw   = (blockIdx.x * blockDim.x + threadIdx.x) >> 5;
    int lane = threadIdx.x & 31;
    if (gw >= N_NODES) return;
    const uint2* g2 = (const uint2*)d_gh;
    float4 s = h4_to_f4(g2[(size_t)gw * 32 + lane]);
    int e0 = d_rowptr[gw], e1 = d_rowptr[gw + 1];
    int e = e0;
    for (; e + 4 <= e1; e += 4) {
        int s0 = __ldg(&d_col[e]),     s1 = __ldg(&d_col[e + 1]);
        int s2 = __ldg(&d_col[e + 2]), s3 = __ldg(&d_col[e + 3]);
        uint2 v0 = __ldg(&g2[(size_t)s0 * 32 + lane]);
        uint2 v1 = __ldg(&g2[(size_t)s1 * 32 + lane]);
        uint2 v2 = __ldg(&g2[(size_t)s2 * 32 + lane]);
        uint2 v3 = __ldg(&g2[(size_t)s3 * 32 + lane]);
        float4 f0 = h4_to_f4(v0), f1 = h4_to_f4(v1), f2 = h4_to_f4(v2), f3 = h4_to_f4(v3);
        s.x += (f0.x + f1.x) + (f2.x + f3.x);
        s.y += (f0.y + f1.y) + (f2.y + f3.y);
        s.z += (f0.z + f1.z) + (f2.z + f3.z);
        s.w += (f0.w + f1.w) + (f2.w + f3.w);
    }
    for (; e < e1; e++) {
        float4 f = h4_to_f4(__ldg(&g2[(size_t)__ldg(&d_col[e]) * 32 + lane]));
        s.x += f.x; s.y += f.y; s.z += f.z; s.w += f.w;
    }
    float dj = d_dinv[gw];
    float4 bb = ((const float4*)b1)[lane];
    float4 o;
    o.x = fmaxf(fmaf(s.x, dj, bb.x), 0.f) * dj;
    o.y = fmaxf(fmaf(s.y, dj, bb.y), 0.f) * dj;
    o.z = fmaxf(fmaf(s.z, dj, bb.z), 0.f) * dj;
    o.w = fmaxf(fmaf(s.w, dj, bb.w), 0.f) * dj;
    ((uint2*)d_g2h)[(size_t)gw * 32 + lane] = f4_to_h4(o);
}

// ---------------- 7. layer-2 aggregate + pool atomics + fused final GEMM --------
__global__ __launch_bounds__(256) void k_agg2f(const int* __restrict__ batch,
                                               const float* __restrict__ W2,
                                               const float* __restrict__ b2,
                                               float* __restrict__ out) {
    int tid  = threadIdx.x;
    int gw   = (blockIdx.x * blockDim.x + tid) >> 5;
    int lane = tid & 31;
    if (gw < N_NODES) {
        const uint2* g2 = (const uint2*)d_g2h;
        float4 s = h4_to_f4(g2[(size_t)gw * 32 + lane]);
        int e0 = d_rowptr[gw], e1 = d_rowptr[gw + 1];
        int e = e0;
        for (; e + 4 <= e1; e += 4) {
            int s0 = __ldg(&d_col[e]),     s1 = __ldg(&d_col[e + 1]);
            int s2 = __ldg(&d_col[e + 2]), s3 = __ldg(&d_col[e + 3]);
            uint2 v0 = __ldg(&g2[(size_t)s0 * 32 + lane]);
            uint2 v1 = __ldg(&g2[(size_t)s1 * 32 + lane]);
            uint2 v2 = __ldg(&g2[(size_t)s2 * 32 + lane]);
            uint2 v3 = __ldg(&g2[(size_t)s3 * 32 + lane]);
            float4 f0 = h4_to_f4(v0), f1 = h4_to_f4(v1),
                   f2 = h4_to_f4(v2), f3 = h4_to_f4(v3);
            s.x += (f0.x + f1.x) + (f2.x + f3.x);
            s.y += (f0.y + f1.y) + (f2.y + f3.y);
            s.z += (f0.z + f1.z) + (f2.z + f3.z);
            s.w += (f0.w + f1.w) + (f2.w + f3.w);
        }
        for (; e < e1; e++) {
            float4 f = h4_to_f4(__ldg(&g2[(size_t)__ldg(&d_col[e]) * 32 + lane]));
            s.x += f.x; s.y += f.y; s.z += f.z; s.w += f.w;
        }
        float dj = d_dinv[gw];
        int bg = min(max(batch[gw], 0), N_GRAPHS - 1);
        float* p = &d_pool[bg * HID_C + lane * 4];
        atomicAdd(p + 0, s.x * dj);
        atomicAdd(p + 1, s.y * dj);
        atomicAdd(p + 2, s.z * dj);
        atomicAdd(p + 3, s.w * dj);
    }
    // ---- last-block fused final ----
    __threadfence();
    __shared__ bool isLast;
    if (tid == 0) {
        unsigned t = atomicAdd(&d_done, 1u);
        isLast = (t == gridDim.x - 1);
        if (isLast) d_done = 0;            // reset for next replay
    }
    __syncthreads();
    if (!isLast) return;
    __threadfence();
    int g = tid >> 2;                      // 64 graphs
    int c0 = (tid & 3) * 16;               // 16 output cols per thread
    int cnt = d_start[g + 1] - d_start[g];
    float inv = 1.0f / (float)max(cnt, 1);
    float acc[16];
    #pragma unroll
    for (int j = 0; j < 16; j++) acc[j] = 0.f;
    for (int k = 0; k < HID_C; k++) {
        float pv = d_pool[g * HID_C + k];
        #pragma unroll
        for (int j = 0; j < 16; j++)
            acc[j] = fmaf(pv, __ldg(&W2[k * OUT_C + c0 + j]), acc[j]);
    }
    #pragma unroll
    for (int j = 0; j < 16; j++)
        out[g * OUT_C + c0 + j] = acc[j] * inv + (cnt > 0 ? __ldg(&b2[c0 + j]) : 0.f);
}

// ---------------- launch (single stream, 7 launches) ----------------
extern "C" void kernel_launch(void* const* d_in, const int* in_sizes, int n_in,
                              void* d_out, int out_size) {
    const float *x = nullptr, *W1 = nullptr, *b1 = nullptr, *W2 = nullptr, *b2 = nullptr;
    const int *edge = nullptr, *batch = nullptr;
    for (int i = 0; i < n_in; i++) {
        switch (in_sizes[i]) {
            case N_NODES * IN_C:  x     = (const float*)d_in[i]; break;
            case IN_C * HID_C:    W1    = (const float*)d_in[i]; break;
            case HID_C:           b1    = (const float*)d_in[i]; break;
            case HID_C * OUT_C:   W2    = (const float*)d_in[i]; break;
            case OUT_C:           b2    = (const float*)d_in[i]; break;
            case 2 * N_EDGES:     edge  = (const int*)d_in[i];   break;
            case N_NODES:         batch = (const int*)d_in[i];   break;
            default: break;
        }
    }

    cudaFuncSetAttribute(k_gemm1, cudaFuncAttributeMaxDynamicSharedMemorySize,
                         GEMM_SMEM_BYTES);

    k_hist<<<(N_EDGES / 4 + 255) / 256, 256>>>(edge);
    k_scanA<<<NBLK, 256>>>();
    k_scanC<<<NBLK, 256>>>(batch);
    k_scatter<<<(N_EDGES / 4 + 255) / 256, 256>>>(edge);   // profiled slot (4th)
    k_gemm1<<<(N_NODES + 127) / 128, 256, GEMM_SMEM_BYTES>>>(x, W1);
    k_agg1<<<(N_NODES + 7) / 8, 256>>>(b1);
    k_agg2f<<<(N_NODES + 7) / 8, 256>>>(batch, W2, b2, (float*)d_out);
}

// round 7
// speedup vs baseline: 1.5895x; 1.5238x over previous
#include <cuda_runtime.h>
#include <cuda_fp16.h>
#include <mma.h>
#include <math.h>

using namespace nvcuda;

#define N_NODES  50000
#define N_EDGES  600000
#define N_GRAPHS 64
#define IN_C  128
#define HID_C 128
#define OUT_C 64
#define NBLK  196            // ceil(50000/256)

// ---------------- scratch (device globals; no allocation allowed) ----------------
__device__ int    d_cnt[N_NODES];
__device__ int    d_rowptr[N_NODES + 1];
__device__ int    d_cursor[N_NODES];
__device__ int    d_part[NBLK];
__device__ int    d_col[N_EDGES];
__device__ float  d_dinv[N_NODES];
__device__ __half d_gh [N_NODES * HID_C];   // dinv * (x @ W1), fp16
__device__ __half d_g2h[N_NODES * HID_C];   // dinv * relu(...), fp16
__device__ float  d_pool[N_GRAPHS * HID_C];
__device__ int    d_start[N_GRAPHS + 1];

// ---------------- helpers ----------------
__device__ __forceinline__ float4 h4_to_f4(uint2 u) {
    __half2 a = *(__half2*)&u.x, b = *(__half2*)&u.y;
    float2 fa = __half22float2(a), fb = __half22float2(b);
    return make_float4(fa.x, fa.y, fb.x, fb.y);
}
__device__ __forceinline__ uint2 f4_to_h4(float4 v) {
    __half2 a = __floats2half2_rn(v.x, v.y), b = __floats2half2_rn(v.z, v.w);
    uint2 u; u.x = *(unsigned*)&a; u.y = *(unsigned*)&b; return u;
}

// ---------------- init ----------------
__global__ void k_init() {
    int i = blockIdx.x * blockDim.x + threadIdx.x;
    if (i < N_NODES) d_cnt[i] = 0;
    if (i < N_GRAPHS * HID_C) d_pool[i] = 0.0f;
}

// ---------------- histogram over dst ----------------
__global__ void k_hist(const int* __restrict__ edge) {
    int e = blockIdx.x * blockDim.x + threadIdx.x;
    if (e >= N_EDGES) return;
    unsigned dst = (unsigned)edge[N_EDGES + e];
    if (dst < N_NODES) atomicAdd(&d_cnt[dst], 1);
}

// ---------------- scan A: per-block excl scan + block totals ----------------
__global__ __launch_bounds__(256) void k_scanA() {
    __shared__ int wsum[8];
    int tid = threadIdx.x, lane = tid & 31, wid = tid >> 5;
    int i = blockIdx.x * 256 + tid;
    int v = (i < N_NODES) ? d_cnt[i] : 0;
    int x = v;
    #pragma unroll
    for (int d = 1; d < 32; d <<= 1) {
        int t = __shfl_up_sync(0xffffffffu, x, d);
        if (lane >= d) x += t;
    }
    if (lane == 31) wsum[wid] = x;
    __syncthreads();
    if (wid == 0 && lane < 8) {
        int y = wsum[lane];
        #pragma unroll
        for (int d = 1; d < 8; d <<= 1) {
            int t = __shfl_up_sync(0x000000ffu, y, d);
            if (lane >= d) y += t;
        }
        wsum[lane] = y;
    }
    __syncthreads();
    int excl = (x - v) + (wid > 0 ? wsum[wid - 1] : 0);
    if (i < N_NODES) d_cursor[i] = excl;
    if (tid == 0) d_part[blockIdx.x] = wsum[7];
}

// ---------------- scan B: scan 196 block totals ----------------
__global__ __launch_bounds__(256) void k_scanB() {
    __shared__ int s[256];
    int t = threadIdx.x;
    int v = (t < NBLK) ? d_part[t] : 0;
    s[t] = v; __syncthreads();
    for (int off = 1; off < 256; off <<= 1) {
        int u = (t >= off) ? s[t - off] : 0;
        __syncthreads();
        s[t] += u;
        __syncthreads();
    }
    if (t < NBLK) d_part[t] = s[t] - v;
    if (t == 255) d_rowptr[N_NODES] = s[255];
}

// ---------------- scan C: fixup + dinv + graph boundaries ----------------
__global__ __launch_bounds__(256) void k_scanC(const int* __restrict__ batch) {
    int i = blockIdx.x * 256 + threadIdx.x;
    if (i >= N_NODES) return;
    int v = d_cursor[i] + d_part[blockIdx.x];
    d_rowptr[i] = v;
    d_cursor[i] = v;
    d_dinv[i] = rsqrtf((float)(d_cnt[i] + 1));
    int b  = min(max(batch[i], 0), N_GRAPHS - 1);
    int bp = (i == 0) ? -1 : min(max(batch[i - 1], 0), N_GRAPHS - 1);
    for (int gg = bp + 1; gg <= b; gg++) d_start[gg] = i;
    if (i == N_NODES - 1)
        for (int gg = b + 1; gg <= N_GRAPHS; gg++) d_start[gg] = N_NODES;
}

// ---------------- CSR scatter ----------------
__global__ void k_scatter(const int* __restrict__ edge) {
    int e = blockIdx.x * blockDim.x + threadIdx.x;
    if (e >= N_EDGES) return;
    unsigned src = (unsigned)edge[e];
    unsigned dst = (unsigned)edge[N_EDGES + e];
    if (src >= N_NODES || dst >= N_NODES) return;
    int p = atomicAdd(&d_cursor[dst], 1);
    d_col[p] = (int)src;
}

// ---------------- GEMM1 (tensor cores): d_gh = fp16( dinv * (x @ W1) ) ----------
#define ASTR 136
#define GEMM_SMEM_BYTES (2 * 128 * ASTR * 2)
__global__ __launch_bounds__(256) void k_gemm1(const float* __restrict__ x,
                                               const float* __restrict__ W1) {
    extern __shared__ char smraw[];
    __half* As = (__half*)smraw;
    __half* Bs = As + 128 * ASTR;
    float*  Cs = (float*)smraw;
    int row0 = blockIdx.x * 128;
    int tid = threadIdx.x, wid = tid >> 5;

    for (int i = tid; i < 4096; i += 256) {
        int r = i >> 5, c4 = i & 31;
        int gr = row0 + r;
        float4 v = make_float4(0.f, 0.f, 0.f, 0.f);
        if (gr < N_NODES) v = ((const float4*)(x + (size_t)gr * IN_C))[c4];
        *(uint2*)&As[r * ASTR + c4 * 4] = f4_to_h4(v);
    }
    for (int i = tid; i < 4096; i += 256) {
        int r = i >> 5, c4 = i & 31;
        float4 v = ((const float4*)W1)[i];
        *(uint2*)&Bs[r * ASTR + c4 * 4] = f4_to_h4(v);
    }
    __syncthreads();

    wmma::fragment<wmma::accumulator, 16, 16, 16, float> acc[8];
    #pragma unroll
    for (int n = 0; n < 8; n++) wmma::fill_fragment(acc[n], 0.0f);

    #pragma unroll
    for (int kk = 0; kk < 8; kk++) {
        wmma::fragment<wmma::matrix_a, 16, 16, 16, __half, wmma::row_major> af;
        wmma::load_matrix_sync(af, &As[(wid * 16) * ASTR + kk * 16], ASTR);
        #pragma unroll
        for (int n = 0; n < 8; n++) {
            wmma::fragment<wmma::matrix_b, 16, 16, 16, __half, wmma::row_major> bf;
            wmma::load_matrix_sync(bf, &Bs[(kk * 16) * ASTR + n * 16], ASTR);
            wmma::mma_sync(acc[n], af, bf, acc[n]);
        }
    }
    __syncthreads();   // done reading As/Bs; Cs aliases them

    #pragma unroll
    for (int n = 0; n < 8; n++)
        wmma::store_matrix_sync(&Cs[(wid * 16) * 128 + n * 16], acc[n], 128,
                                wmma::mem_row_major);
    __syncthreads();

    for (int i = tid; i < 4096; i += 256) {
        int r = i >> 5, c4 = i & 31;
        int gr = row0 + r;
        if (gr < N_NODES) {
            float dv = d_dinv[gr];
            float4 v = *(float4*)&Cs[r * 128 + c4 * 4];
            v.x *= dv; v.y *= dv; v.z *= dv; v.w *= dv;
            *(uint2*)&d_gh[(size_t)gr * HID_C + c4 * 4] = f4_to_h4(v);
        }
    }
}

// ---------------- layer-1 aggregate: warp per node ----------------
__global__ __launch_bounds__(256) void k_agg1(const float* __restrict__ b1) {
    int gw   = (blockIdx.x * blockDim.x + threadIdx.x) >> 5;
    int lane = threadIdx.x & 31;
    if (gw >= N_NODES) return;
    const uint2* g2 = (const uint2*)d_gh;
    float4 s = h4_to_f4(g2[(size_t)gw * 32 + lane]);
    int e0 = d_rowptr[gw], e1 = d_rowptr[gw + 1];
    int e = e0;
    for (; e + 4 <= e1; e += 4) {
        int s0 = __ldg(&d_col[e]),     s1 = __ldg(&d_col[e + 1]);
        int s2 = __ldg(&d_col[e + 2]), s3 = __ldg(&d_col[e + 3]);
        uint2 v0 = __ldg(&g2[(size_t)s0 * 32 + lane]);
        uint2 v1 = __ldg(&g2[(size_t)s1 * 32 + lane]);
        uint2 v2 = __ldg(&g2[(size_t)s2 * 32 + lane]);
        uint2 v3 = __ldg(&g2[(size_t)s3 * 32 + lane]);
        float4 f0 = h4_to_f4(v0), f1 = h4_to_f4(v1), f2 = h4_to_f4(v2), f3 = h4_to_f4(v3);
        s.x += (f0.x + f1.x) + (f2.x + f3.x);
        s.y += (f0.y + f1.y) + (f2.y + f3.y);
        s.z += (f0.z + f1.z) + (f2.z + f3.z);
        s.w += (f0.w + f1.w) + (f2.w + f3.w);
    }
    for (; e < e1; e++) {
        float4 f = h4_to_f4(__ldg(&g2[(size_t)__ldg(&d_col[e]) * 32 + lane]));
        s.x += f.x; s.y += f.y; s.z += f.z; s.w += f.w;
    }
    float dj = d_dinv[gw];
    float4 bb = ((const float4*)b1)[lane];
    float4 o;
    o.x = fmaxf(fmaf(s.x, dj, bb.x), 0.f) * dj;
    o.y = fmaxf(fmaf(s.y, dj, bb.y), 0.f) * dj;
    o.z = fmaxf(fmaf(s.z, dj, bb.z), 0.f) * dj;
    o.w = fmaxf(fmaf(s.w, dj, bb.w), 0.f) * dj;
    ((uint2*)d_g2h)[(size_t)gw * 32 + lane] = f4_to_h4(o);
}

// ---------------- layer-2 aggregate + pool atomics ----------------
__global__ __launch_bounds__(256) void k_agg2(const int* __restrict__ batch) {
    int gw   = (blockIdx.x * blockDim.x + threadIdx.x) >> 5;
    int lane = threadIdx.x & 31;
    if (gw >= N_NODES) return;
    const uint2* g2 = (const uint2*)d_g2h;
    float4 s = h4_to_f4(g2[(size_t)gw * 32 + lane]);
    int e0 = d_rowptr[gw], e1 = d_rowptr[gw + 1];
    int e = e0;
    for (; e + 4 <= e1; e += 4) {
        int s0 = __ldg(&d_col[e]),     s1 = __ldg(&d_col[e + 1]);
        int s2 = __ldg(&d_col[e + 2]), s3 = __ldg(&d_col[e + 3]);
        uint2 v0 = __ldg(&g2[(size_t)s0 * 32 + lane]);
        uint2 v1 = __ldg(&g2[(size_t)s1 * 32 + lane]);
        uint2 v2 = __ldg(&g2[(size_t)s2 * 32 + lane]);
        uint2 v3 = __ldg(&g2[(size_t)s3 * 32 + lane]);
        float4 f0 = h4_to_f4(v0), f1 = h4_to_f4(v1), f2 = h4_to_f4(v2), f3 = h4_to_f4(v3);
        s.x += (f0.x + f1.x) + (f2.x + f3.x);
        s.y += (f0.y + f1.y) + (f2.y + f3.y);
        s.z += (f0.z + f1.z) + (f2.z + f3.z);
        s.w += (f0.w + f1.w) + (f2.w + f3.w);
    }
    for (; e < e1; e++) {
        float4 f = h4_to_f4(__ldg(&g2[(size_t)__ldg(&d_col[e]) * 32 + lane]));
        s.x += f.x; s.y += f.y; s.z += f.z; s.w += f.w;
    }
    float dj = d_dinv[gw];
    int bg = min(max(batch[gw], 0), N_GRAPHS - 1);
    float* p = &d_pool[bg * HID_C + lane * 4];
    atomicAdd(p + 0, s.x * dj);
    atomicAdd(p + 1, s.y * dj);
    atomicAdd(p + 2, s.z * dj);
    atomicAdd(p + 3, s.w * dj);
}

// ---------------- final: out = (pool/cnt) @ W2 + b2 ----------------
__global__ void k_final(const float* __restrict__ W2, const float* __restrict__ b2,
                        float* __restrict__ out) {
    __shared__ float ps[HID_C];
    int g = blockIdx.x;
    int t = threadIdx.x; // 128 threads
    int cnt = d_start[g + 1] - d_start[g];
    float inv = 1.0f / (float)max(cnt, 1);
    ps[t] = d_pool[g * HID_C + t];
    __syncthreads();
    if (t < OUT_C) {
        float sum = 0.f;
        #pragma unroll
        for (int k = 0; k < HID_C; k++)
            sum = fmaf(ps[k], W2[k * OUT_C + t], sum);
        out[g * OUT_C + t] = sum * inv + (cnt > 0 ? b2[t] : 0.f);
    }
}

// ---------------- launch ----------------
extern "C" void kernel_launch(void* const* d_in, const int* in_sizes, int n_in,
                              void* d_out, int out_size) {
    const float *x = nullptr, *W1 = nullptr, *b1 = nullptr, *W2 = nullptr, *b2 = nullptr;
    const int *edge = nullptr, *batch = nullptr;
    for (int i = 0; i < n_in; i++) {
        switch (in_sizes[i]) {
            case N_NODES * IN_C:  x     = (const float*)d_in[i]; break;
            case IN_C * HID_C:    W1    = (const float*)d_in[i]; break;
            case HID_C:           b1    = (const float*)d_in[i]; break;
            case HID_C * OUT_C:   W2    = (const float*)d_in[i]; break;
            case OUT_C:           b2    = (const float*)d_in[i]; break;
            case 2 * N_EDGES:     edge  = (const int*)d_in[i];   break;
            case N_NODES:         batch = (const int*)d_in[i];   break;
            default: break;
        }
    }

    cudaFuncSetAttribute(k_gemm1, cudaFuncAttributeMaxDynamicSharedMemorySize,
                         GEMM_SMEM_BYTES);

    k_init<<<(N_NODES + 255) / 256, 256>>>();
    k_hist<<<(N_EDGES + 255) / 256, 256>>>(edge);
    k_scanA<<<NBLK, 256>>>();
    k_scanB<<<1, 256>>>();
    k_scanC<<<NBLK, 256>>>(batch);
    k_scatter<<<(N_EDGES + 255) / 256, 256>>>(edge);
    k_gemm1<<<(N_NODES + 127) / 128, 256, GEMM_SMEM_BYTES>>>(x, W1);
    k_agg1<<<(N_NODES + 7) / 8, 256>>>(b1);
    k_agg2<<<(N_NODES + 7) / 8, 256>>>(batch);
    k_final<<<N_GRAPHS, 128>>>(W2, b2, (float*)d_out);
}